// round 16
// baseline (speedup 1.0000x reference)
#include <cuda_runtime.h>
#include <cuda_bf16.h>
#include <cstdint>

#define NB 32768
#define ND 512
#define NSPLIT_G 16
#define KSPLIT_G (NB / NSPLIT_G)   // 2048 elements of K per gram split

#define N_GRAM_JOBS (2 * 10 * NSPLIT_G)            // 320, 32 dual-chunk stages, hi-only
#define N_FWD_JOBS  (2 * (NB / 128) * (ND / 128))  // 2048, 16 stages, 3 combos
// total = 2368 = 8 * 296 resident CTAs: exact wave quantization

// ---------------------------------------------------------------------------
// Scratch (device globals: no allocation allowed)
// ---------------------------------------------------------------------------
__device__ float g_stim[(size_t)NB * ND];                    // 64 MB
__device__ float g_rec[(size_t)NB * ND];                     // 64 MB
__device__ __nv_bfloat16 g_s_split[2][(size_t)NB * 1024];    // 128 MB  [b][hi|lo]
__device__ __nv_bfloat16 g_st_hi[2][(size_t)ND * NB];        // 64 MB   [i][hi over b]
__device__ __nv_bfloat16 g_wt_split[2][(size_t)ND * 1024];   // 2 MB    Wt[n][hi|lo over k]
__device__ float g_gram[2][NSPLIT_G][ND * ND];               // 32 MB   split-K partials

// ---------------------------------------------------------------------------
// PTX helpers (sm_80+ compatible: cp.async, ldmatrix, mma.sync bf16)
// ---------------------------------------------------------------------------
__device__ __forceinline__ uint32_t smem_to_u32(const void* p) {
    uint32_t a;
    asm("{ .reg .u64 t; cvta.to.shared.u64 t, %1; cvt.u32.u64 %0, t; }"
        : "=r"(a) : "l"(p));
    return a;
}

#define CP16(dst, src) \
    asm volatile("cp.async.cg.shared.global [%0], [%1], 16;" :: "r"(dst), "l"(src))
#define CP_COMMIT() asm volatile("cp.async.commit_group;")
#define CP_WAIT0() asm volatile("cp.async.wait_group 0;")

__device__ __forceinline__ void ldsm4(uint32_t* r, uint32_t addr) {
    asm volatile("ldmatrix.sync.aligned.m8n8.x4.shared.b16 {%0,%1,%2,%3}, [%4];"
                 : "=r"(r[0]), "=r"(r[1]), "=r"(r[2]), "=r"(r[3]) : "r"(addr));
}

__device__ __forceinline__ void mma16816(float* d, const uint32_t* a, const uint32_t* b) {
    asm volatile(
        "mma.sync.aligned.m16n8k16.row.col.f32.bf16.bf16.f32 "
        "{%0,%1,%2,%3}, {%4,%5,%6,%7}, {%8,%9}, {%0,%1,%2,%3};"
        : "+f"(d[0]), "+f"(d[1]), "+f"(d[2]), "+f"(d[3])
        : "r"(a[0]), "r"(a[1]), "r"(a[2]), "r"(a[3]), "r"(b[0]), "r"(b[1]));
}

__device__ __forceinline__ uint32_t packbf2(__nv_bfloat16 a, __nv_bfloat16 b) {
    return (uint32_t)__bfloat16_as_ushort(a) | ((uint32_t)__bfloat16_as_ushort(b) << 16);
}

// smem tile: 128 rows x 32 bf16 (64B), padded stride 80B (conflict-free ldmatrix)
#define TROWB 80
#define TILEB (128 * TROWB)        // 10240 B
#define STAGEB (4 * TILEB)         // 4 tile slots = 40960 B
#define PIPE_SMEM (2 * STAGEB)     // 81920 B dynamic

// 4-tile stage loader; slots: [s0, s1, s2, s3] = +0, +TILEB, +2T, +3T
__device__ __forceinline__ void load_stage4(uint32_t sm,
                                            const __nv_bfloat16* A0,
                                            const __nv_bfloat16* A1, size_t sA,
                                            const __nv_bfloat16* B0,
                                            const __nv_bfloat16* B1, size_t sB, int t) {
#pragma unroll
    for (int r = 0; r < 2; r++) {
        int c = t + r * 256;
        int row = c >> 2, ch = c & 3;
        uint32_t d = row * TROWB + ch * 16;
        size_t ga = (size_t)row * sA + ch * 8;
        size_t gb = (size_t)row * sB + ch * 8;
        CP16(sm + d, A0 + ga);
        CP16(sm + TILEB + d, A1 + ga);
        CP16(sm + 2 * TILEB + d, B0 + gb);
        CP16(sm + 3 * TILEB + d, B1 + gb);
    }
}

// per-thread ldmatrix offsets (byte offsets within a tile buffer)
struct LaneOff {
    uint32_t a[2];   // mt = 0,1
    uint32_t b[4];   // nt pairs 0..3
};
__device__ __forceinline__ LaneOff make_offsets(int t) {
    int w = t >> 5, l = t & 31;
    int wm = w & 3, wn = w >> 2;
    int mat = l >> 3, lrow = l & 7;
    LaneOff o;
#pragma unroll
    for (int mt = 0; mt < 2; mt++) {
        int m = wm * 32 + mt * 16 + (mat & 1) * 8 + lrow;
        int k = (mat >> 1) * 8;
        o.a[mt] = m * TROWB + k * 2;
    }
#pragma unroll
    for (int q = 0; q < 4; q++) {
        int n = wn * 64 + q * 16 + (l >> 4) * 8 + lrow;
        int k = ((l >> 3) & 1) * 8;
        o.b[q] = n * TROWB + k * 2;
    }
    return o;
}

// one 32-K pass over a resident (A, B) tile pair
__device__ __forceinline__ void compute_pass(uint32_t smA, uint32_t smB,
                                             const LaneOff& o, float acc[2][8][4]) {
#pragma unroll
    for (int ks = 0; ks < 2; ks++) {
        uint32_t a[2][4], b[4][4];
        ldsm4(a[0], smA + o.a[0] + ks * 32);
        ldsm4(a[1], smA + o.a[1] + ks * 32);
#pragma unroll
        for (int q = 0; q < 4; q++) ldsm4(b[q], smB + o.b[q] + ks * 32);
#pragma unroll
        for (int mt = 0; mt < 2; mt++)
#pragma unroll
            for (int nt = 0; nt < 8; nt++)
                mma16816(acc[mt][nt], a[mt], &b[nt >> 1][(nt & 1) * 2]);
    }
}

// fwd: all 3 split combos with fragment reuse (HH, HL reuse aHi, LH reuse bHi)
__device__ __forceinline__ void compute_stage3(uint32_t sm, const LaneOff& o,
                                               float acc[2][8][4]) {
    const uint32_t Ahi = sm, Alo = sm + TILEB;
    const uint32_t Bhi = sm + 2 * TILEB, Blo = sm + 3 * TILEB;
#pragma unroll
    for (int ks = 0; ks < 2; ks++) {
        uint32_t ah[2][4], al[2][4], bh[4][4], bl[4][4];
        ldsm4(ah[0], Ahi + o.a[0] + ks * 32);
        ldsm4(ah[1], Ahi + o.a[1] + ks * 32);
#pragma unroll
        for (int q = 0; q < 4; q++) ldsm4(bh[q], Bhi + o.b[q] + ks * 32);
#pragma unroll
        for (int mt = 0; mt < 2; mt++)
#pragma unroll
            for (int nt = 0; nt < 8; nt++)
                mma16816(acc[mt][nt], ah[mt], &bh[nt >> 1][(nt & 1) * 2]);
#pragma unroll
        for (int q = 0; q < 4; q++) ldsm4(bl[q], Blo + o.b[q] + ks * 32);
#pragma unroll
        for (int mt = 0; mt < 2; mt++)
#pragma unroll
            for (int nt = 0; nt < 8; nt++)
                mma16816(acc[mt][nt], ah[mt], &bl[nt >> 1][(nt & 1) * 2]);
        ldsm4(al[0], Alo + o.a[0] + ks * 32);
        ldsm4(al[1], Alo + o.a[1] + ks * 32);
#pragma unroll
        for (int mt = 0; mt < 2; mt++)
#pragma unroll
            for (int nt = 0; nt < 8; nt++)
                mma16816(acc[mt][nt], al[mt], &bh[nt >> 1][(nt & 1) * 2]);
    }
}

// gram dual-chunk stage: slots = A@k0, A@k0+32, B@k0, B@k0+32
__device__ __forceinline__ void compute_stage1x2(uint32_t sm, const LaneOff& o,
                                                 float acc[2][8][4]) {
    compute_pass(sm, sm + 2 * TILEB, o, acc);            // chunk 0
    compute_pass(sm + TILEB, sm + 3 * TILEB, o, acc);    // chunk 1
}

// ---------------------------------------------------------------------------
// P1: W/Wr -> transposed bf16 split  Wt[n][k] (k: 0..511 hi, 512..1023 lo)
// ---------------------------------------------------------------------------
__global__ void wsplit_kernel(const float* __restrict__ W, const float* __restrict__ Wr) {
    __shared__ float tile[32][33];
    int mat = blockIdx.z;
    const float* src = mat ? Wr : W;
    __nv_bfloat16* dst = g_wt_split[mat];
    int k0 = blockIdx.x * 32, n0 = blockIdx.y * 32;
    int tx = threadIdx.x, ty = threadIdx.y;
    for (int ry = ty; ry < 32; ry += 8)
        tile[ry][tx] = src[(size_t)(k0 + ry) * ND + n0 + tx];
    __syncthreads();
    for (int ry = ty; ry < 32; ry += 8) {
        float v = tile[tx][ry];
        __nv_bfloat16 hi = __float2bfloat16(v);
        __nv_bfloat16 lo = __float2bfloat16(v - __bfloat162float(hi));
        dst[(size_t)(n0 + ry) * 1024 + k0 + tx] = hi;
        dst[(size_t)(n0 + ry) * 1024 + 512 + k0 + tx] = lo;
    }
}

// ---------------------------------------------------------------------------
// P2: S/P -> row-major bf16 split [b][hi|lo] and transposed hi [i][b]
//     8-byte packed stores (4 bf16 per store)
// ---------------------------------------------------------------------------
__global__ __launch_bounds__(256) void ssplit_kernel(const float* __restrict__ S,
                                                     const float* __restrict__ P) {
    __shared__ float tile[128][33];
    int mat = blockIdx.z;
    const float* src = mat ? P : S;
    __nv_bfloat16* drow = g_s_split[mat];
    __nv_bfloat16* dcol = g_st_hi[mat];
    int b0 = blockIdx.x * 128, c0 = blockIdx.y * 32;
    int t = threadIdx.x;
#pragma unroll
    for (int j = 0; j < 16; j++) {
        int idx = t + 256 * j;
        int r = idx >> 5, c = idx & 31;
        tile[r][c] = src[(size_t)(b0 + r) * ND + c0 + c];
    }
    __syncthreads();
    // row-major hi|lo: thread handles 4 consecutive cols -> two 8B stores
#pragma unroll
    for (int j = 0; j < 4; j++) {
        int idx = t + 256 * j;
        int r = idx >> 3, cp = (idx & 7) * 4;
        __nv_bfloat16 h[4], lo[4];
#pragma unroll
        for (int q = 0; q < 4; q++) {
            float v = tile[r][cp + q];
            h[q] = __float2bfloat16(v);
            lo[q] = __float2bfloat16(v - __bfloat162float(h[q]));
        }
        uint2 ph = make_uint2(packbf2(h[0], h[1]), packbf2(h[2], h[3]));
        uint2 pl = make_uint2(packbf2(lo[0], lo[1]), packbf2(lo[2], lo[3]));
        *(uint2*)&drow[(size_t)(b0 + r) * 1024 + c0 + cp] = ph;
        *(uint2*)&drow[(size_t)(b0 + r) * 1024 + 512 + c0 + cp] = pl;
    }
    // transposed hi: thread handles 4 consecutive b -> one 8B store
#pragma unroll
    for (int j = 0; j < 4; j++) {
        int idx = t + 256 * j;
        int il = idx >> 5, bp = (idx & 31) * 4;
        __nv_bfloat16 h[4];
#pragma unroll
        for (int q = 0; q < 4; q++)
            h[q] = __float2bfloat16(tile[bp + q][il]);
        uint2 ph = make_uint2(packbf2(h[0], h[1]), packbf2(h[2], h[3]));
        *(uint2*)&dcol[(size_t)(c0 + il) * NB + b0 + bp] = ph;
    }
}

// ---------------------------------------------------------------------------
// K1: unified MMA kernel, single-sync double-buffered pipeline.
//   jobs [0, 320):     gram tiles (32 dual-chunk stages, hi-only) -- first
//   jobs [320, 2368):  fwd tiles (16 stages, 3 combos)
//   total 2368 = exactly 8 waves of 296 resident CTAs
// ---------------------------------------------------------------------------
__global__ __launch_bounds__(256, 2) void mma_all() {
    extern __shared__ __align__(128) char dynsm[];
    const int TI_[10] = {0, 0, 0, 0, 1, 1, 1, 2, 2, 3};
    const int TJ_[10] = {0, 1, 2, 3, 1, 2, 3, 2, 3, 3};
    int t = threadIdx.x;
    int job = blockIdx.x;

    uint32_t smb[2] = {smem_to_u32(dynsm), smem_to_u32(dynsm) + STAGEB};
    LaneOff o = make_offsets(t);
    float acc[2][8][4];
#pragma unroll
    for (int i = 0; i < 2; i++)
#pragma unroll
        for (int j = 0; j < 8; j++)
#pragma unroll
            for (int q = 0; q < 4; q++) acc[i][j][q] = 0.f;

    float* Out;

    if (job < N_GRAM_JOBS) {
        int mat = job / (N_GRAM_JOBS / 2);
        int r = job % (N_GRAM_JOBS / 2);
        int sp = r / 10, tile = r % 10;   // sp-major: concurrent jobs share strips
        int i0 = TI_[tile] * 128, j0 = TJ_[tile] * 128;
        const __nv_bfloat16* Sg = g_st_hi[mat];
        size_t kb = (size_t)sp * KSPLIT_G;
        const __nv_bfloat16* Ah0 = Sg + (size_t)i0 * NB + kb;
        const __nv_bfloat16* Bh0 = Sg + (size_t)j0 * NB + kb;
        Out = g_gram[mat][sp] + (size_t)i0 * ND + j0;
        const int nst = KSPLIT_G / 64;   // 32 dual-chunk stages

        auto issue = [&](int i, int buf) {
            const __nv_bfloat16* Ab = Ah0 + i * 64;
            const __nv_bfloat16* Bb = Bh0 + i * 64;
            load_stage4(smb[buf], Ab, Ab + 32, NB, Bb, Bb + 32, NB, t);
            CP_COMMIT();
        };
        issue(0, 0);
        for (int i = 0; i < nst; i++) {
            int buf = i & 1;
            CP_WAIT0();
            __syncthreads();
            if (i + 1 < nst) issue(i + 1, buf ^ 1);
            compute_stage1x2(smb[buf], o, acc);
        }
    } else {
        int f = job - N_GRAM_JOBS;
        int mat = f / (N_FWD_JOBS / 2);
        int r = f % (N_FWD_JOBS / 2);
        int n0 = (r & 3) * 128, m0 = (r >> 2) * 128;
        const __nv_bfloat16* Ah0 = g_s_split[mat] + (size_t)m0 * 1024;
        const __nv_bfloat16* Bh0 = g_wt_split[mat] + (size_t)n0 * 1024;
        Out = (mat ? g_rec : g_stim) + (size_t)m0 * ND + n0;
        const int nst = ND / 32;   // 16

        auto issue = [&](int i, int buf) {
            const __nv_bfloat16* Ab = Ah0 + i * 32;
            const __nv_bfloat16* Bb = Bh0 + i * 32;
            load_stage4(smb[buf], Ab, Ab + 512, 1024, Bb, Bb + 512, 1024, t);
            CP_COMMIT();
        };
        issue(0, 0);
        for (int i = 0; i < nst; i++) {
            int buf = i & 1;
            CP_WAIT0();
            __syncthreads();
            if (i + 1 < nst) issue(i + 1, buf ^ 1);
            compute_stage3(smb[buf], o, acc);
        }
    }

    __syncthreads();
    int w = t >> 5, l = t & 31;
    int wm = w & 3, wn = w >> 2;
#pragma unroll
    for (int mt = 0; mt < 2; mt++)
#pragma unroll
        for (int nt = 0; nt < 8; nt++) {
            int m = wm * 32 + mt * 16 + (l >> 2);
            int n = wn * 64 + nt * 8 + (l & 3) * 2;
            *(float2*)&Out[(size_t)m * ND + n] = make_float2(acc[mt][nt][0], acc[mt][nt][1]);
            *(float2*)&Out[(size_t)(m + 8) * ND + n] = make_float2(acc[mt][nt][2], acc[mt][nt][3]);
        }
}

// ---------------------------------------------------------------------------
// K3: rec LN -> relu(stim + rec_norm) -> final LN.
//     2 rows per 256-thread block; each row uses 128 lane-contiguous threads.
// ---------------------------------------------------------------------------
__global__ __launch_bounds__(256) void ln_kernel(float* __restrict__ out,
                                                 const float* __restrict__ rg,
                                                 const float* __restrict__ rb,
                                                 const float* __restrict__ ag,
                                                 const float* __restrict__ ab) {
    __shared__ float2 sbuf[2][4];
    __shared__ float2 sbuf2[2][4];
    int t = threadIdx.x;
    int half = t >> 7;           // row within block
    int th = t & 127;            // thread within row
    int w = th >> 5, l = th & 31;
    size_t base = ((size_t)blockIdx.x * 2 + half) * ND;

    float4 r4 = *(const float4*)&g_rec[base + th * 4];
    float2 s = make_float2(r4.x + r4.y + r4.z + r4.w,
                           r4.x * r4.x + r4.y * r4.y + r4.z * r4.z + r4.w * r4.w);
#pragma unroll
    for (int o = 16; o > 0; o >>= 1) {
        s.x += __shfl_xor_sync(0xffffffffu, s.x, o);
        s.y += __shfl_xor_sync(0xffffffffu, s.y, o);
    }
    if (l == 0) sbuf[half][w] = s;
    __syncthreads();
    s = make_float2(sbuf[half][0].x + sbuf[half][1].x + sbuf[half][2].x + sbuf[half][3].x,
                    sbuf[half][0].y + sbuf[half][1].y + sbuf[half][2].y + sbuf[half][3].y);
    float mu = s.x * (1.f / ND);
    float var = s.y * (1.f / ND) - mu * mu;
    float inv = rsqrtf(var + 1e-5f);

    float4 g4 = *(const float4*)&rg[th * 4];
    float4 b4 = *(const float4*)&rb[th * 4];
    float4 st4 = *(const float4*)&g_stim[base + th * 4];
    float4 x4;
    x4.x = fmaxf(st4.x + (r4.x - mu) * inv * g4.x + b4.x, 0.f);
    x4.y = fmaxf(st4.y + (r4.y - mu) * inv * g4.y + b4.y, 0.f);
    x4.z = fmaxf(st4.z + (r4.z - mu) * inv * g4.z + b4.z, 0.f);
    x4.w = fmaxf(st4.w + (r4.w - mu) * inv * g4.w + b4.w, 0.f);

    float2 s2 = make_float2(x4.x + x4.y + x4.z + x4.w,
                            x4.x * x4.x + x4.y * x4.y + x4.z * x4.z + x4.w * x4.w);
#pragma unroll
    for (int o = 16; o > 0; o >>= 1) {
        s2.x += __shfl_xor_sync(0xffffffffu, s2.x, o);
        s2.y += __shfl_xor_sync(0xffffffffu, s2.y, o);
    }
    if (l == 0) sbuf2[half][w] = s2;
    __syncthreads();
    s2 = make_float2(sbuf2[half][0].x + sbuf2[half][1].x + sbuf2[half][2].x + sbuf2[half][3].x,
                     sbuf2[half][0].y + sbuf2[half][1].y + sbuf2[half][2].y + sbuf2[half][3].y);
    float mu2 = s2.x * (1.f / ND);
    float var2 = s2.y * (1.f / ND) - mu2 * mu2;
    float inv2 = rsqrtf(var2 + 1e-5f);

    float4 ag4 = *(const float4*)&ag[th * 4];
    float4 ab4 = *(const float4*)&ab[th * 4];
    float4 o4;
    o4.x = (x4.x - mu2) * inv2 * ag4.x + ab4.x;
    o4.y = (x4.y - mu2) * inv2 * ag4.y + ab4.y;
    o4.z = (x4.z - mu2) * inv2 * ag4.z + ab4.z;
    o4.w = (x4.w - mu2) * inv2 * ag4.w + ab4.w;
    *(float4*)&out[base + th * 4] = o4;
}

// ---------------------------------------------------------------------------
// K4: weight update: sum gram splits (mirror lower tiles), heb = G @ Wm,
//     scale, l2-normalize rows. 256 blocks x 4 rows, 256 threads.
// ---------------------------------------------------------------------------
__global__ __launch_bounds__(256) void update_kernel(float* __restrict__ out_base,
                                                     const float* __restrict__ W,
                                                     const float* __restrict__ Wr,
                                                     const float* __restrict__ alpha,
                                                     const float* __restrict__ decay) {
    int z = blockIdx.x;        // 0..255
    int mat = z >> 7;
    int i0 = (z & 127) * 4;
    const float* Wm = mat ? Wr : W;
    float* o = out_base + (size_t)NB * ND + (size_t)mat * ND * ND;

    __shared__ float g[4][ND];
    __shared__ float sv[4][ND];
    __shared__ float norms[4];

    int t = threadIdx.x;
    for (int idx = t; idx < 4 * ND; idx += 256) {
        int r = idx >> 9, c = idx & 511;
        int i = i0 + r;
        size_t off = ((i >> 7) <= (c >> 7)) ? (size_t)i * ND + c : (size_t)c * ND + i;
        float s = 0.f;
#pragma unroll
        for (int sp = 0; sp < NSPLIT_G; sp++) s += g_gram[mat][sp][off];
        g[r][c] = s;
    }
    __syncthreads();

    float acc[4][2] = {};
    for (int k0 = 0; k0 < ND; k0 += 8) {
        float w0[8], w1[8];
#pragma unroll
        for (int u = 0; u < 8; u++) {
            w0[u] = Wm[(size_t)(k0 + u) * ND + t];
            w1[u] = Wm[(size_t)(k0 + u) * ND + t + 256];
        }
#pragma unroll
        for (int u = 0; u < 8; u++) {
#pragma unroll
            for (int r = 0; r < 4; r++) {
                float gk = g[r][k0 + u];
                acc[r][0] = fmaf(gk, w0[u], acc[r][0]);
                acc[r][1] = fmaf(gk, w1[u], acc[r][1]);
            }
        }
    }

    float a0 = alpha[t], a1 = alpha[t + 256];
#pragma unroll
    for (int r = 0; r < 4; r++) {
        float dm = 1.f - decay[i0 + r];
        sv[r][t]       = Wm[(size_t)(i0 + r) * ND + t] * dm       + acc[r][0] * a0;
        sv[r][t + 256] = Wm[(size_t)(i0 + r) * ND + t + 256] * dm + acc[r][1] * a1;
    }
    __syncthreads();

    int w = t >> 5, l = t & 31;
    if (w < 4) {
        float s = 0.f;
#pragma unroll
        for (int c = l; c < ND; c += 32) {
            float v = sv[w][c];
            s += v * v;
        }
#pragma unroll
        for (int o2 = 16; o2 > 0; o2 >>= 1) s += __shfl_xor_sync(0xffffffffu, s, o2);
        if (l == 0) norms[w] = fmaxf(sqrtf(s), 1e-12f);
    }
    __syncthreads();

#pragma unroll
    for (int r = 0; r < 4; r++) {
        float inv = 1.f / norms[r];
        o[(size_t)(i0 + r) * ND + t]       = sv[r][t] * inv;
        o[(size_t)(i0 + r) * ND + t + 256] = sv[r][t + 256] * inv;
    }
}

// ---------------------------------------------------------------------------
extern "C" void kernel_launch(void* const* d_in, const int* in_sizes, int n_in,
                              void* d_out, int out_size) {
    const float* S     = (const float*)d_in[0];
    const float* P     = (const float*)d_in[1];
    const float* W     = (const float*)d_in[2];
    const float* Wr    = (const float*)d_in[3];
    const float* alpha = (const float*)d_in[4];
    const float* decay = (const float*)d_in[5];
    const float* ag    = (const float*)d_in[6];
    const float* ab    = (const float*)d_in[7];
    const float* rg    = (const float*)d_in[8];
    const float* rb    = (const float*)d_in[9];
    float* out = (float*)d_out;

    cudaFuncSetAttribute(mma_all, cudaFuncAttributeMaxDynamicSharedMemorySize, PIPE_SMEM);

    wsplit_kernel<<<dim3(16, 16, 2), dim3(32, 8)>>>(W, Wr);
    ssplit_kernel<<<dim3(NB / 128, ND / 32, 2), 256>>>(S, P);
    mma_all<<<N_GRAM_JOBS + N_FWD_JOBS, 256, PIPE_SMEM>>>();
    ln_kernel<<<NB / 2, 256>>>(out, rg, rb, ag, ab);
    update_kernel<<<256, 256>>>(out, W, Wr, alpha, decay);
}

// round 17
// speedup vs baseline: 1.0035x; 1.0035x over previous
#include <cuda_runtime.h>
#include <cuda_bf16.h>
#include <cstdint>

#define NB 32768
#define ND 512
#define NSPLIT_G 16
#define KSPLIT_G (NB / NSPLIT_G)   // 2048 elements of K per gram split

#define N_GRAM_JOBS (2 * 10 * NSPLIT_G)            // 320, 32 dual-chunk stages, hi-only
#define N_FWD_JOBS  (2 * (NB / 128) * (ND / 128))  // 2048, 16 stages, 3 combos
// total = 2368 = 8 * 296 resident CTAs: exact wave quantization

// ---------------------------------------------------------------------------
// Scratch (device globals: no allocation allowed)
// ---------------------------------------------------------------------------
__device__ float g_stim[(size_t)NB * ND];                    // 64 MB
__device__ float g_rec[(size_t)NB * ND];                     // 64 MB
__device__ __nv_bfloat16 g_s_split[2][(size_t)NB * 1024];    // 128 MB  [b][hi|lo]
__device__ __nv_bfloat16 g_st_hi[2][(size_t)ND * NB];        // 64 MB   [i][hi over b]
__device__ __nv_bfloat16 g_wt_split[2][(size_t)ND * 1024];   // 2 MB    Wt[n][hi|lo over k]
__device__ float g_gram[2][NSPLIT_G][ND * ND];               // 32 MB   split-K partials

// ---------------------------------------------------------------------------
// PTX helpers (sm_80+ compatible: cp.async, ldmatrix, mma.sync bf16)
// ---------------------------------------------------------------------------
__device__ __forceinline__ uint32_t smem_to_u32(const void* p) {
    uint32_t a;
    asm("{ .reg .u64 t; cvta.to.shared.u64 t, %1; cvt.u32.u64 %0, t; }"
        : "=r"(a) : "l"(p));
    return a;
}

#define CP16(dst, src) \
    asm volatile("cp.async.cg.shared.global [%0], [%1], 16;" :: "r"(dst), "l"(src))
#define CP_COMMIT() asm volatile("cp.async.commit_group;")
#define CP_WAIT0() asm volatile("cp.async.wait_group 0;")

__device__ __forceinline__ void ldsm4(uint32_t* r, uint32_t addr) {
    asm volatile("ldmatrix.sync.aligned.m8n8.x4.shared.b16 {%0,%1,%2,%3}, [%4];"
                 : "=r"(r[0]), "=r"(r[1]), "=r"(r[2]), "=r"(r[3]) : "r"(addr));
}

__device__ __forceinline__ void mma16816(float* d, const uint32_t* a, const uint32_t* b) {
    asm volatile(
        "mma.sync.aligned.m16n8k16.row.col.f32.bf16.bf16.f32 "
        "{%0,%1,%2,%3}, {%4,%5,%6,%7}, {%8,%9}, {%0,%1,%2,%3};"
        : "+f"(d[0]), "+f"(d[1]), "+f"(d[2]), "+f"(d[3])
        : "r"(a[0]), "r"(a[1]), "r"(a[2]), "r"(a[3]), "r"(b[0]), "r"(b[1]));
}

__device__ __forceinline__ uint32_t packbf2(__nv_bfloat16 a, __nv_bfloat16 b) {
    return (uint32_t)__bfloat16_as_ushort(a) | ((uint32_t)__bfloat16_as_ushort(b) << 16);
}

// smem tile: 128 rows x 32 bf16 (64B), padded stride 80B (conflict-free ldmatrix)
#define TROWB 80
#define TILEB (128 * TROWB)        // 10240 B
#define STAGEB (4 * TILEB)         // 4 tile slots = 40960 B
#define PIPE_SMEM (2 * STAGEB)     // 81920 B dynamic

// 4-tile stage loader; slots: [s0, s1, s2, s3] = +0, +TILEB, +2T, +3T
__device__ __forceinline__ void load_stage4(uint32_t sm,
                                            const __nv_bfloat16* A0,
                                            const __nv_bfloat16* A1, size_t sA,
                                            const __nv_bfloat16* B0,
                                            const __nv_bfloat16* B1, size_t sB, int t) {
#pragma unroll
    for (int r = 0; r < 2; r++) {
        int c = t + r * 256;
        int row = c >> 2, ch = c & 3;
        uint32_t d = row * TROWB + ch * 16;
        size_t ga = (size_t)row * sA + ch * 8;
        size_t gb = (size_t)row * sB + ch * 8;
        CP16(sm + d, A0 + ga);
        CP16(sm + TILEB + d, A1 + ga);
        CP16(sm + 2 * TILEB + d, B0 + gb);
        CP16(sm + 3 * TILEB + d, B1 + gb);
    }
}

// per-thread ldmatrix offsets (byte offsets within a tile buffer)
struct LaneOff {
    uint32_t a[2];   // mt = 0,1
    uint32_t b[4];   // nt pairs 0..3
};
__device__ __forceinline__ LaneOff make_offsets(int t) {
    int w = t >> 5, l = t & 31;
    int wm = w & 3, wn = w >> 2;
    int mat = l >> 3, lrow = l & 7;
    LaneOff o;
#pragma unroll
    for (int mt = 0; mt < 2; mt++) {
        int m = wm * 32 + mt * 16 + (mat & 1) * 8 + lrow;
        int k = (mat >> 1) * 8;
        o.a[mt] = m * TROWB + k * 2;
    }
#pragma unroll
    for (int q = 0; q < 4; q++) {
        int n = wn * 64 + q * 16 + (l >> 4) * 8 + lrow;
        int k = ((l >> 3) & 1) * 8;
        o.b[q] = n * TROWB + k * 2;
    }
    return o;
}

// one 32-K pass over a resident (A, B) tile pair
__device__ __forceinline__ void compute_pass(uint32_t smA, uint32_t smB,
                                             const LaneOff& o, float acc[2][8][4]) {
#pragma unroll
    for (int ks = 0; ks < 2; ks++) {
        uint32_t a[2][4], b[4][4];
        ldsm4(a[0], smA + o.a[0] + ks * 32);
        ldsm4(a[1], smA + o.a[1] + ks * 32);
#pragma unroll
        for (int q = 0; q < 4; q++) ldsm4(b[q], smB + o.b[q] + ks * 32);
#pragma unroll
        for (int mt = 0; mt < 2; mt++)
#pragma unroll
            for (int nt = 0; nt < 8; nt++)
                mma16816(acc[mt][nt], a[mt], &b[nt >> 1][(nt & 1) * 2]);
    }
}

// fwd: all 3 split combos with fragment reuse (HH, HL reuse aHi, LH reuse bHi)
__device__ __forceinline__ void compute_stage3(uint32_t sm, const LaneOff& o,
                                               float acc[2][8][4]) {
    const uint32_t Ahi = sm, Alo = sm + TILEB;
    const uint32_t Bhi = sm + 2 * TILEB, Blo = sm + 3 * TILEB;
#pragma unroll
    for (int ks = 0; ks < 2; ks++) {
        uint32_t ah[2][4], al[2][4], bh[4][4], bl[4][4];
        ldsm4(ah[0], Ahi + o.a[0] + ks * 32);
        ldsm4(ah[1], Ahi + o.a[1] + ks * 32);
#pragma unroll
        for (int q = 0; q < 4; q++) ldsm4(bh[q], Bhi + o.b[q] + ks * 32);
#pragma unroll
        for (int mt = 0; mt < 2; mt++)
#pragma unroll
            for (int nt = 0; nt < 8; nt++)
                mma16816(acc[mt][nt], ah[mt], &bh[nt >> 1][(nt & 1) * 2]);
#pragma unroll
        for (int q = 0; q < 4; q++) ldsm4(bl[q], Blo + o.b[q] + ks * 32);
#pragma unroll
        for (int mt = 0; mt < 2; mt++)
#pragma unroll
            for (int nt = 0; nt < 8; nt++)
                mma16816(acc[mt][nt], ah[mt], &bl[nt >> 1][(nt & 1) * 2]);
        ldsm4(al[0], Alo + o.a[0] + ks * 32);
        ldsm4(al[1], Alo + o.a[1] + ks * 32);
#pragma unroll
        for (int mt = 0; mt < 2; mt++)
#pragma unroll
            for (int nt = 0; nt < 8; nt++)
                mma16816(acc[mt][nt], al[mt], &bh[nt >> 1][(nt & 1) * 2]);
    }
}

// gram dual-chunk stage: slots = A@k0, A@k0+32, B@k0, B@k0+32
__device__ __forceinline__ void compute_stage1x2(uint32_t sm, const LaneOff& o,
                                                 float acc[2][8][4]) {
    compute_pass(sm, sm + 2 * TILEB, o, acc);            // chunk 0
    compute_pass(sm + TILEB, sm + 3 * TILEB, o, acc);    // chunk 1
}

// ---------------------------------------------------------------------------
// P1: W/Wr -> transposed bf16 split  Wt[n][k] (k: 0..511 hi, 512..1023 lo)
// ---------------------------------------------------------------------------
__global__ void wsplit_kernel(const float* __restrict__ W, const float* __restrict__ Wr) {
    __shared__ float tile[32][33];
    int mat = blockIdx.z;
    const float* src = mat ? Wr : W;
    __nv_bfloat16* dst = g_wt_split[mat];
    int k0 = blockIdx.x * 32, n0 = blockIdx.y * 32;
    int tx = threadIdx.x, ty = threadIdx.y;
    for (int ry = ty; ry < 32; ry += 8)
        tile[ry][tx] = src[(size_t)(k0 + ry) * ND + n0 + tx];
    __syncthreads();
    for (int ry = ty; ry < 32; ry += 8) {
        float v = tile[tx][ry];
        __nv_bfloat16 hi = __float2bfloat16(v);
        __nv_bfloat16 lo = __float2bfloat16(v - __bfloat162float(hi));
        dst[(size_t)(n0 + ry) * 1024 + k0 + tx] = hi;
        dst[(size_t)(n0 + ry) * 1024 + 512 + k0 + tx] = lo;
    }
}

// ---------------------------------------------------------------------------
// P2: S/P -> row-major bf16 split [b][hi|lo] and transposed hi [i][b]
//     8-byte packed stores (4 bf16 per store)
// ---------------------------------------------------------------------------
__global__ __launch_bounds__(256) void ssplit_kernel(const float* __restrict__ S,
                                                     const float* __restrict__ P) {
    __shared__ float tile[128][33];
    int mat = blockIdx.z;
    const float* src = mat ? P : S;
    __nv_bfloat16* drow = g_s_split[mat];
    __nv_bfloat16* dcol = g_st_hi[mat];
    int b0 = blockIdx.x * 128, c0 = blockIdx.y * 32;
    int t = threadIdx.x;
#pragma unroll
    for (int j = 0; j < 16; j++) {
        int idx = t + 256 * j;
        int r = idx >> 5, c = idx & 31;
        tile[r][c] = src[(size_t)(b0 + r) * ND + c0 + c];
    }
    __syncthreads();
    // row-major hi|lo: thread handles 4 consecutive cols -> two 8B stores
#pragma unroll
    for (int j = 0; j < 4; j++) {
        int idx = t + 256 * j;
        int r = idx >> 3, cp = (idx & 7) * 4;
        __nv_bfloat16 h[4], lo[4];
#pragma unroll
        for (int q = 0; q < 4; q++) {
            float v = tile[r][cp + q];
            h[q] = __float2bfloat16(v);
            lo[q] = __float2bfloat16(v - __bfloat162float(h[q]));
        }
        uint2 ph = make_uint2(packbf2(h[0], h[1]), packbf2(h[2], h[3]));
        uint2 pl = make_uint2(packbf2(lo[0], lo[1]), packbf2(lo[2], lo[3]));
        *(uint2*)&drow[(size_t)(b0 + r) * 1024 + c0 + cp] = ph;
        *(uint2*)&drow[(size_t)(b0 + r) * 1024 + 512 + c0 + cp] = pl;
    }
    // transposed hi: thread handles 4 consecutive b -> one 8B store
#pragma unroll
    for (int j = 0; j < 4; j++) {
        int idx = t + 256 * j;
        int il = idx >> 5, bp = (idx & 31) * 4;
        __nv_bfloat16 h[4];
#pragma unroll
        for (int q = 0; q < 4; q++)
            h[q] = __float2bfloat16(tile[bp + q][il]);
        uint2 ph = make_uint2(packbf2(h[0], h[1]), packbf2(h[2], h[3]));
        *(uint2*)&dcol[(size_t)(c0 + il) * NB + b0 + bp] = ph;
    }
}

// ---------------------------------------------------------------------------
// K1: unified MMA kernel, single-sync double-buffered pipeline.
//   jobs [0, 320):     gram tiles (32 dual-chunk stages, hi-only) -- first
//   jobs [320, 2368):  fwd tiles (16 stages, 3 combos)
//   total 2368 = exactly 8 waves of 296 resident CTAs
// ---------------------------------------------------------------------------
__global__ __launch_bounds__(256, 2) void mma_all() {
    extern __shared__ __align__(128) char dynsm[];
    const int TI_[10] = {0, 0, 0, 0, 1, 1, 1, 2, 2, 3};
    const int TJ_[10] = {0, 1, 2, 3, 1, 2, 3, 2, 3, 3};
    int t = threadIdx.x;
    int job = blockIdx.x;

    uint32_t smb[2] = {smem_to_u32(dynsm), smem_to_u32(dynsm) + STAGEB};
    LaneOff o = make_offsets(t);
    float acc[2][8][4];
#pragma unroll
    for (int i = 0; i < 2; i++)
#pragma unroll
        for (int j = 0; j < 8; j++)
#pragma unroll
            for (int q = 0; q < 4; q++) acc[i][j][q] = 0.f;

    float* Out;

    if (job < N_GRAM_JOBS) {
        int mat = job / (N_GRAM_JOBS / 2);
        int r = job % (N_GRAM_JOBS / 2);
        int sp = r / 10, tile = r % 10;   // sp-major: concurrent jobs share strips
        int i0 = TI_[tile] * 128, j0 = TJ_[tile] * 128;
        const __nv_bfloat16* Sg = g_st_hi[mat];
        size_t kb = (size_t)sp * KSPLIT_G;
        const __nv_bfloat16* Ah0 = Sg + (size_t)i0 * NB + kb;
        const __nv_bfloat16* Bh0 = Sg + (size_t)j0 * NB + kb;
        Out = g_gram[mat][sp] + (size_t)i0 * ND + j0;
        const int nst = KSPLIT_G / 64;   // 32 dual-chunk stages

        auto issue = [&](int i, int buf) {
            const __nv_bfloat16* Ab = Ah0 + i * 64;
            const __nv_bfloat16* Bb = Bh0 + i * 64;
            load_stage4(smb[buf], Ab, Ab + 32, NB, Bb, Bb + 32, NB, t);
            CP_COMMIT();
        };
        issue(0, 0);
        for (int i = 0; i < nst; i++) {
            int buf = i & 1;
            CP_WAIT0();
            __syncthreads();
            if (i + 1 < nst) issue(i + 1, buf ^ 1);
            compute_stage1x2(smb[buf], o, acc);
        }
    } else {
        int f = job - N_GRAM_JOBS;
        int mat = f / (N_FWD_JOBS / 2);
        int r = f % (N_FWD_JOBS / 2);
        int n0 = (r & 3) * 128, m0 = (r >> 2) * 128;
        const __nv_bfloat16* Ah0 = g_s_split[mat] + (size_t)m0 * 1024;
        const __nv_bfloat16* Bh0 = g_wt_split[mat] + (size_t)n0 * 1024;
        Out = (mat ? g_rec : g_stim) + (size_t)m0 * ND + n0;
        const int nst = ND / 32;   // 16

        auto issue = [&](int i, int buf) {
            const __nv_bfloat16* Ab = Ah0 + i * 32;
            const __nv_bfloat16* Bb = Bh0 + i * 32;
            load_stage4(smb[buf], Ab, Ab + 512, 1024, Bb, Bb + 512, 1024, t);
            CP_COMMIT();
        };
        issue(0, 0);
        for (int i = 0; i < nst; i++) {
            int buf = i & 1;
            CP_WAIT0();
            __syncthreads();
            if (i + 1 < nst) issue(i + 1, buf ^ 1);
            compute_stage3(smb[buf], o, acc);
        }
    }

    __syncthreads();
    int w = t >> 5, l = t & 31;
    int wm = w & 3, wn = w >> 2;
#pragma unroll
    for (int mt = 0; mt < 2; mt++)
#pragma unroll
        for (int nt = 0; nt < 8; nt++) {
            int m = wm * 32 + mt * 16 + (l >> 2);
            int n = wn * 64 + nt * 8 + (l & 3) * 2;
            *(float2*)&Out[(size_t)m * ND + n] = make_float2(acc[mt][nt][0], acc[mt][nt][1]);
            *(float2*)&Out[(size_t)(m + 8) * ND + n] = make_float2(acc[mt][nt][2], acc[mt][nt][3]);
        }
}

// ---------------------------------------------------------------------------
// K3: rec LN -> relu(stim + rec_norm) -> final LN.
//     2 rows per 256-thread block; each row uses 128 lane-contiguous threads.
// ---------------------------------------------------------------------------
__global__ __launch_bounds__(256) void ln_kernel(float* __restrict__ out,
                                                 const float* __restrict__ rg,
                                                 const float* __restrict__ rb,
                                                 const float* __restrict__ ag,
                                                 const float* __restrict__ ab) {
    __shared__ float2 sbuf[2][4];
    __shared__ float2 sbuf2[2][4];
    int t = threadIdx.x;
    int half = t >> 7;           // row within block
    int th = t & 127;            // thread within row
    int w = th >> 5, l = th & 31;
    size_t base = ((size_t)blockIdx.x * 2 + half) * ND;

    float4 r4 = *(const float4*)&g_rec[base + th * 4];
    float2 s = make_float2(r4.x + r4.y + r4.z + r4.w,
                           r4.x * r4.x + r4.y * r4.y + r4.z * r4.z + r4.w * r4.w);
#pragma unroll
    for (int o = 16; o > 0; o >>= 1) {
        s.x += __shfl_xor_sync(0xffffffffu, s.x, o);
        s.y += __shfl_xor_sync(0xffffffffu, s.y, o);
    }
    if (l == 0) sbuf[half][w] = s;
    __syncthreads();
    s = make_float2(sbuf[half][0].x + sbuf[half][1].x + sbuf[half][2].x + sbuf[half][3].x,
                    sbuf[half][0].y + sbuf[half][1].y + sbuf[half][2].y + sbuf[half][3].y);
    float mu = s.x * (1.f / ND);
    float var = s.y * (1.f / ND) - mu * mu;
    float inv = rsqrtf(var + 1e-5f);

    float4 g4 = *(const float4*)&rg[th * 4];
    float4 b4 = *(const float4*)&rb[th * 4];
    float4 st4 = *(const float4*)&g_stim[base + th * 4];
    float4 x4;
    x4.x = fmaxf(st4.x + (r4.x - mu) * inv * g4.x + b4.x, 0.f);
    x4.y = fmaxf(st4.y + (r4.y - mu) * inv * g4.y + b4.y, 0.f);
    x4.z = fmaxf(st4.z + (r4.z - mu) * inv * g4.z + b4.z, 0.f);
    x4.w = fmaxf(st4.w + (r4.w - mu) * inv * g4.w + b4.w, 0.f);

    float2 s2 = make_float2(x4.x + x4.y + x4.z + x4.w,
                            x4.x * x4.x + x4.y * x4.y + x4.z * x4.z + x4.w * x4.w);
#pragma unroll
    for (int o = 16; o > 0; o >>= 1) {
        s2.x += __shfl_xor_sync(0xffffffffu, s2.x, o);
        s2.y += __shfl_xor_sync(0xffffffffu, s2.y, o);
    }
    if (l == 0) sbuf2[half][w] = s2;
    __syncthreads();
    s2 = make_float2(sbuf2[half][0].x + sbuf2[half][1].x + sbuf2[half][2].x + sbuf2[half][3].x,
                     sbuf2[half][0].y + sbuf2[half][1].y + sbuf2[half][2].y + sbuf2[half][3].y);
    float mu2 = s2.x * (1.f / ND);
    float var2 = s2.y * (1.f / ND) - mu2 * mu2;
    float inv2 = rsqrtf(var2 + 1e-5f);

    float4 ag4 = *(const float4*)&ag[th * 4];
    float4 ab4 = *(const float4*)&ab[th * 4];
    float4 o4;
    o4.x = (x4.x - mu2) * inv2 * ag4.x + ab4.x;
    o4.y = (x4.y - mu2) * inv2 * ag4.y + ab4.y;
    o4.z = (x4.z - mu2) * inv2 * ag4.z + ab4.z;
    o4.w = (x4.w - mu2) * inv2 * ag4.w + ab4.w;
    *(float4*)&out[base + th * 4] = o4;
}

// ---------------------------------------------------------------------------
// K4: weight update: sum gram splits (mirror lower tiles), heb = G @ Wm,
//     scale, l2-normalize rows. 256 blocks x 4 rows, 256 threads.
// ---------------------------------------------------------------------------
__global__ __launch_bounds__(256) void update_kernel(float* __restrict__ out_base,
                                                     const float* __restrict__ W,
                                                     const float* __restrict__ Wr,
                                                     const float* __restrict__ alpha,
                                                     const float* __restrict__ decay) {
    int z = blockIdx.x;        // 0..255
    int mat = z >> 7;
    int i0 = (z & 127) * 4;
    const float* Wm = mat ? Wr : W;
    float* o = out_base + (size_t)NB * ND + (size_t)mat * ND * ND;

    __shared__ float g[4][ND];
    __shared__ float sv[4][ND];
    __shared__ float norms[4];

    int t = threadIdx.x;
    for (int idx = t; idx < 4 * ND; idx += 256) {
        int r = idx >> 9, c = idx & 511;
        int i = i0 + r;
        size_t off = ((i >> 7) <= (c >> 7)) ? (size_t)i * ND + c : (size_t)c * ND + i;
        float s = 0.f;
#pragma unroll
        for (int sp = 0; sp < NSPLIT_G; sp++) s += g_gram[mat][sp][off];
        g[r][c] = s;
    }
    __syncthreads();

    float acc[4][2] = {};
    for (int k0 = 0; k0 < ND; k0 += 8) {
        float w0[8], w1[8];
#pragma unroll
        for (int u = 0; u < 8; u++) {
            w0[u] = Wm[(size_t)(k0 + u) * ND + t];
            w1[u] = Wm[(size_t)(k0 + u) * ND + t + 256];
        }
#pragma unroll
        for (int u = 0; u < 8; u++) {
#pragma unroll
            for (int r = 0; r < 4; r++) {
                float gk = g[r][k0 + u];
                acc[r][0] = fmaf(gk, w0[u], acc[r][0]);
                acc[r][1] = fmaf(gk, w1[u], acc[r][1]);
            }
        }
    }

    float a0 = alpha[t], a1 = alpha[t + 256];
#pragma unroll
    for (int r = 0; r < 4; r++) {
        float dm = 1.f - decay[i0 + r];
        sv[r][t]       = Wm[(size_t)(i0 + r) * ND + t] * dm       + acc[r][0] * a0;
        sv[r][t + 256] = Wm[(size_t)(i0 + r) * ND + t + 256] * dm + acc[r][1] * a1;
    }
    __syncthreads();

    int w = t >> 5, l = t & 31;
    if (w < 4) {
        float s = 0.f;
#pragma unroll
        for (int c = l; c < ND; c += 32) {
            float v = sv[w][c];
            s += v * v;
        }
#pragma unroll
        for (int o2 = 16; o2 > 0; o2 >>= 1) s += __shfl_xor_sync(0xffffffffu, s, o2);
        if (l == 0) norms[w] = fmaxf(sqrtf(s), 1e-12f);
    }
    __syncthreads();

#pragma unroll
    for (int r = 0; r < 4; r++) {
        float inv = 1.f / norms[r];
        o[(size_t)(i0 + r) * ND + t]       = sv[r][t] * inv;
        o[(size_t)(i0 + r) * ND + t + 256] = sv[r][t + 256] * inv;
    }
}

// ---------------------------------------------------------------------------
extern "C" void kernel_launch(void* const* d_in, const int* in_sizes, int n_in,
                              void* d_out, int out_size) {
    const float* S     = (const float*)d_in[0];
    const float* P     = (const float*)d_in[1];
    const float* W     = (const float*)d_in[2];
    const float* Wr    = (const float*)d_in[3];
    const float* alpha = (const float*)d_in[4];
    const float* decay = (const float*)d_in[5];
    const float* ag    = (const float*)d_in[6];
    const float* ab    = (const float*)d_in[7];
    const float* rg    = (const float*)d_in[8];
    const float* rb    = (const float*)d_in[9];
    float* out = (float*)d_out;

    cudaFuncSetAttribute(mma_all, cudaFuncAttributeMaxDynamicSharedMemorySize, PIPE_SMEM);

    wsplit_kernel<<<dim3(16, 16, 2), dim3(32, 8)>>>(W, Wr);
    ssplit_kernel<<<dim3(NB / 128, ND / 32, 2), 256>>>(S, P);
    mma_all<<<N_GRAM_JOBS + N_FWD_JOBS, 256, PIPE_SMEM>>>();
    ln_kernel<<<NB / 2, 256>>>(out, rg, rb, ag, ab);
    update_kernel<<<256, 256>>>(out, W, Wr, alpha, decay);
}